// round 1
// baseline (speedup 1.0000x reference)
#include <cuda_runtime.h>
#include <math.h>

#define SEQ 1024
#define BATCH 8
#define MTOT (BATCH*SEQ)   // 8192
#define NHEADS 8
#define DHEAD 64
#define DMODEL 512
#define DIN 524
#define DFF 2048
#define NCLS 1024
#define OUTROW 1036

// ---------------- scratch (device globals; no allocation allowed) ----------------
__device__ float g_x [MTOT*DIN];
__device__ float g_h [MTOT*DMODEL];
__device__ float g_hn[MTOT*DMODEL];
__device__ float g_q [MTOT*DMODEL];
__device__ float g_k [MTOT*DMODEL];
__device__ float g_v [MTOT*DMODEL];
__device__ float g_o [MTOT*DMODEL];
__device__ float g_ff[MTOT*DFF];
__device__ float g_out2[MTOT*DIN];
__device__ float g_bias[NHEADS*SEQ];

// ---------------- relpos bias table ----------------
__global__ void bias_table_kernel(const float* __restrict__ relpos)
{
    int n = blockIdx.x * blockDim.x + threadIdx.x;
    if (n >= SEQ) return;
    int bucket;
    if (n < 4) {
        bucket = n;
    } else {
        int vl = 4 + (int)(logf((float)n * 0.25f) * (4.0f / logf(8.0f)));
        bucket = vl < 7 ? vl : 7;
    }
    for (int h = 0; h < NHEADS; h++)
        g_bias[h*SEQ + n] = relpos[bucket*NHEADS + h] * 8.0f;  // * DIM_HEAD**0.5
}

// ---------------- embedding gather + concat ----------------
__global__ __launch_bounds__(256)
void embed_kernel(const float* __restrict__ saml, const float* __restrict__ emb)
{
    int m = blockIdx.x;              // token index 0..8191
    int b = m >> 10, s = m & 1023;
    const float* row = saml + ((long)b*1025 + s)*13;
    int id = (int)row[0];
    float* x = g_x + (long)m*DIN;
    const float* erow = emb + (long)id*512;
    for (int c = threadIdx.x; c < DIN; c += 256)
        x[c] = (c < 512) ? erow[c] : row[c - 511];
}

// ---------------- generic SGEMM: C = op(A@B [+bias] [+Res]) ----------------
// MODE: 0 plain, 1 +bias, 2 +bias+residual, 3 gelu(+bias)
template<int MODE, bool TSTORE>
__global__ __launch_bounds__(256)
void sgemm_kernel(int M, int N, int K,
                  const float* __restrict__ A, int lda,
                  const float* __restrict__ B, int ldb,
                  const float* __restrict__ bias,
                  const float* __restrict__ Res, int ldr,
                  float* __restrict__ C, int ldc)
{
    __shared__ float As[8*128];
    __shared__ float Bs[8*128];
    const int tid  = threadIdx.x;
    const int row0 = blockIdx.y * 128;
    const int col0 = blockIdx.x * 128;
    const int tr = tid >> 4, tc = tid & 15;
    const int aRow = tid >> 1, aCol = (tid & 1) * 4;
    const int bRow = tid >> 5, bCol = (tid & 31) * 4;

    float acc[8][8];
    #pragma unroll
    for (int i=0;i<8;i++)
        #pragma unroll
        for (int j=0;j<8;j++) acc[i][j]=0.f;

    for (int kt = 0; kt < K; kt += 8) {
        // A tile (row always < M; M multiple of 128 here)
        {
            int k = kt + aCol;
            const float* Ap = A + (long)(row0 + aRow)*lda + k;
            float4 av;
            if (k + 3 < K) av = *(const float4*)Ap;
            else {
                av.x = (k+0<K)?Ap[0]:0.f;
                av.y = (k+1<K)?Ap[1]:0.f;
                av.z = (k+2<K)?Ap[2]:0.f;
                av.w = (k+3<K)?Ap[3]:0.f;
            }
            As[(aCol+0)*128 + aRow] = av.x;
            As[(aCol+1)*128 + aRow] = av.y;
            As[(aCol+2)*128 + aRow] = av.z;
            As[(aCol+3)*128 + aRow] = av.w;
        }
        // B tile
        {
            int k = kt + bRow;
            int c = col0 + bCol;
            float4 bv = make_float4(0.f,0.f,0.f,0.f);
            if (k < K && c < N) bv = *(const float4*)(B + (long)k*ldb + c);
            *(float4*)(&Bs[bRow*128 + bCol]) = bv;
        }
        __syncthreads();
        #pragma unroll
        for (int kk = 0; kk < 8; kk++) {
            float a[8], bb[8];
            #pragma unroll
            for (int i=0;i<8;i++) a[i]  = As[kk*128 + tr*8 + i];
            #pragma unroll
            for (int j=0;j<8;j++) bb[j] = Bs[kk*128 + tc*8 + j];
            #pragma unroll
            for (int i=0;i<8;i++)
                #pragma unroll
                for (int j=0;j<8;j++)
                    acc[i][j] = fmaf(a[i], bb[j], acc[i][j]);
        }
        __syncthreads();
    }
    #pragma unroll
    for (int i=0;i<8;i++) {
        int r = row0 + tr*8 + i;
        #pragma unroll
        for (int j=0;j<8;j++) {
            int c = col0 + tc*8 + j;
            if (c < N) {
                float v = acc[i][j];
                if (MODE >= 1) v += bias[c];
                if (MODE == 2) v += Res[(long)r*ldr + c];
                if (MODE == 3) v = 0.5f*v*(1.f + erff(v*0.7071067811865476f));
                if (TSTORE) {
                    int b_ = r >> 10, s_ = r & 1023;
                    C[(long)b_*(NCLS*OUTROW) + (long)c*OUTROW + s_] = v;
                } else {
                    C[(long)r*ldc + c] = v;
                }
            }
        }
    }
}

// ---------------- scalenorm ----------------
__global__ __launch_bounds__(256)
void scalenorm_kernel(const float* __restrict__ X, float* __restrict__ Y,
                      const float* __restrict__ gptr)
{
    int m = blockIdx.x;
    const float* x = X + (long)m*DMODEL;
    int t = threadIdx.x;
    float v0 = x[t], v1 = x[t+256];
    float ss = v0*v0 + v1*v1;
    #pragma unroll
    for (int off=16; off; off>>=1) ss += __shfl_xor_sync(0xffffffffu, ss, off);
    __shared__ float red[8];
    if ((t & 31) == 0) red[t>>5] = ss;
    __syncthreads();
    __shared__ float tot;
    if (t < 32) {
        float s2 = (t < 8) ? red[t] : 0.f;
        #pragma unroll
        for (int off=4; off; off>>=1) s2 += __shfl_xor_sync(0xffffffffu, s2, off);
        if (t == 0) tot = s2;
    }
    __syncthreads();
    float n = sqrtf(tot) * 0.04419417382415922f;   // * 512^-0.5
    float f = gptr[0] / fmaxf(n, 1e-5f);
    float* y = Y + (long)m*DMODEL;
    y[t] = v0*f; y[t+256] = v1*f;
}

// ---------------- final layernorm (in place) ----------------
__global__ __launch_bounds__(256)
void layernorm_kernel(float* __restrict__ X,
                      const float* __restrict__ gam, const float* __restrict__ bet)
{
    int m = blockIdx.x;
    float* x = X + (long)m*DMODEL;
    int t = threadIdx.x;
    float v0 = x[t], v1 = x[t+256];
    float s1 = v0 + v1, s2 = v0*v0 + v1*v1;
    #pragma unroll
    for (int off=16; off; off>>=1) {
        s1 += __shfl_xor_sync(0xffffffffu, s1, off);
        s2 += __shfl_xor_sync(0xffffffffu, s2, off);
    }
    __shared__ float r1[8], r2[8];
    if ((t & 31) == 0) { r1[t>>5]=s1; r2[t>>5]=s2; }
    __syncthreads();
    __shared__ float mu_s, rs_s;
    if (t < 32) {
        float a = (t<8)?r1[t]:0.f, b = (t<8)?r2[t]:0.f;
        #pragma unroll
        for (int off=4; off; off>>=1) {
            a += __shfl_xor_sync(0xffffffffu, a, off);
            b += __shfl_xor_sync(0xffffffffu, b, off);
        }
        if (t == 0) {
            float mu = a * (1.f/512.f);
            float var = b * (1.f/512.f) - mu*mu;
            mu_s = mu; rs_s = rsqrtf(var + 1e-5f);
        }
    }
    __syncthreads();
    float mu = mu_s, rs = rs_s;
    x[t]     = (v0 - mu)*rs*gam[t]     + bet[t];
    x[t+256] = (v1 - mu)*rs*gam[t+256] + bet[t+256];
}

// ---------------- rotary on q,k (first 32 dims of each head) ----------------
__global__ __launch_bounds__(256)
void rotary_kernel(float* __restrict__ Q, float* __restrict__ Kg)
{
    int idx = blockIdx.x*blockDim.x + threadIdx.x;
    if (idx >= MTOT*NHEADS*16) return;
    int d    = idx & 15;
    int head = (idx >> 4) & 7;
    int m    = idx >> 7;
    int s    = m & 1023;
    float inv = expf(-(float)(2*d) * (9.210340371976184f/32.f));  // 10000^(-2d/32)
    float ang = (float)s * inv;
    float sn, c;
    sincosf(ang, &sn, &c);
    long base = (long)m*DMODEL + head*DHEAD + d;
    float a = Q[base], b = Q[base+16];
    Q[base]    = a*c - b*sn;
    Q[base+16] = b*c + a*sn;
    a = Kg[base]; b = Kg[base+16];
    Kg[base]    = a*c - b*sn;
    Kg[base+16] = b*c + a*sn;
}

// ---------------- flash attention (64x64 tiles, online softmax) ----------------
__global__ __launch_bounds__(256)
void flash_attn_kernel(const float* __restrict__ Q, const float* __restrict__ Kg,
                       const float* __restrict__ Vg, float* __restrict__ O)
{
    __shared__ float Qs[64*64];
    __shared__ float KPs[64*64];   // K tile, later reused for P tile (rotation swizzle)
    __shared__ float Vs[64*64];

    const int tid  = threadIdx.x;
    const int qb   = blockIdx.x;          // 0..15
    const int bh   = blockIdx.y;          // 0..63
    const int b    = bh >> 3, head = bh & 7;
    const int q0   = qb * 64;
    const long base = ((long)b * SEQ) * DMODEL + head * DHEAD;

    const int ty = tid >> 4, tx = tid & 15;
    const int r0 = ty * 4;
    const int c0 = tx * 4;

    for (int idx = tid; idx < 64*16; idx += 256) {
        int rr = idx >> 4, c4 = (idx & 15) * 4;
        float4 v = *(const float4*)(Q + base + (long)(q0+rr)*DMODEL + c4);
        Qs[rr*64+c4+0]=v.x; Qs[rr*64+c4+1]=v.y; Qs[rr*64+c4+2]=v.z; Qs[rr*64+c4+3]=v.w;
    }

    float m_run[4], l_run[4], o[4][4];
    #pragma unroll
    for (int i=0;i<4;i++){ m_run[i]=-3.0e38f; l_run[i]=0.f;
        #pragma unroll
        for (int j=0;j<4;j++) o[i][j]=0.f; }

    for (int kt = 0; kt <= qb; kt++) {
        int k0 = kt * 64;
        __syncthreads();
        for (int idx = tid; idx < 64*16; idx += 256) {
            int jj = idx >> 4, c4 = (idx & 15) * 4;
            float4 kv = *(const float4*)(Kg + base + (long)(k0+jj)*DMODEL + c4);
            KPs[jj*64 + ((c4+0+jj)&63)] = kv.x;
            KPs[jj*64 + ((c4+1+jj)&63)] = kv.y;
            KPs[jj*64 + ((c4+2+jj)&63)] = kv.z;
            KPs[jj*64 + ((c4+3+jj)&63)] = kv.w;
            float4 vv = *(const float4*)(Vg + base + (long)(k0+jj)*DMODEL + c4);
            *(float4*)(&Vs[jj*64 + c4]) = vv;
        }
        __syncthreads();

        float s[4][4];
        #pragma unroll
        for (int i=0;i<4;i++)
            #pragma unroll
            for (int j=0;j<4;j++) s[i][j]=0.f;
        for (int kk = 0; kk < 64; kk++) {
            float qv[4], kv[4];
            #pragma unroll
            for (int i=0;i<4;i++) qv[i] = Qs[(r0+i)*64 + kk];
            #pragma unroll
            for (int j=0;j<4;j++) kv[j] = KPs[(c0+j)*64 + ((kk + c0 + j)&63)];
            #pragma unroll
            for (int i=0;i<4;i++)
                #pragma unroll
                for (int j=0;j<4;j++)
                    s[i][j] = fmaf(qv[i], kv[j], s[i][j]);
        }
        #pragma unroll
        for (int i=0;i<4;i++) {
            int qi = q0 + r0 + i;
            #pragma unroll
            for (int j=0;j<4;j++) {
                int kj = k0 + c0 + j;
                if (kj > qi) s[i][j] = -3.0e38f;
                else         s[i][j] = s[i][j]*0.125f + g_bias[head*SEQ + (qi - kj)];
            }
        }
        #pragma unroll
        for (int i=0;i<4;i++) {
            float mx = fmaxf(fmaxf(s[i][0],s[i][1]),fmaxf(s[i][2],s[i][3]));
            mx = fmaxf(mx, __shfl_xor_sync(0xffffffffu, mx, 8));
            mx = fmaxf(mx, __shfl_xor_sync(0xffffffffu, mx, 4));
            mx = fmaxf(mx, __shfl_xor_sync(0xffffffffu, mx, 2));
            mx = fmaxf(mx, __shfl_xor_sync(0xffffffffu, mx, 1));
            float m_new = fmaxf(m_run[i], mx);
            float alpha = __expf(m_run[i] - m_new);
            float ls = 0.f;
            #pragma unroll
            for (int j=0;j<4;j++) { s[i][j] = __expf(s[i][j] - m_new); ls += s[i][j]; }
            ls += __shfl_xor_sync(0xffffffffu, ls, 8);
            ls += __shfl_xor_sync(0xffffffffu, ls, 4);
            ls += __shfl_xor_sync(0xffffffffu, ls, 2);
            ls += __shfl_xor_sync(0xffffffffu, ls, 1);
            l_run[i] = l_run[i]*alpha + ls;
            m_run[i] = m_new;
            #pragma unroll
            for (int j=0;j<4;j++) o[i][j] *= alpha;
        }
        __syncthreads();
        #pragma unroll
        for (int i=0;i<4;i++){
            int r = r0 + i;
            #pragma unroll
            for (int j=0;j<4;j++)
                KPs[r*64 + ((c0+j+r)&63)] = s[i][j];
        }
        __syncthreads();
        for (int jj = 0; jj < 64; jj++) {
            float pv[4], vv[4];
            #pragma unroll
            for (int i=0;i<4;i++) pv[i] = KPs[(r0+i)*64 + ((jj + r0 + i)&63)];
            #pragma unroll
            for (int j=0;j<4;j++) vv[j] = Vs[jj*64 + c0 + j];
            #pragma unroll
            for (int i=0;i<4;i++)
                #pragma unroll
                for (int j=0;j<4;j++)
                    o[i][j] = fmaf(pv[i], vv[j], o[i][j]);
        }
    }
    #pragma unroll
    for (int i=0;i<4;i++){
        float inv_l = 1.f / l_run[i];
        #pragma unroll
        for (int j=0;j<4;j++)
            O[base + (long)(q0 + r0 + i)*DMODEL + c0 + j] = o[i][j]*inv_l;
    }
}

// ---------------- tail copy (last 12 output columns) ----------------
__global__ void tail_kernel(float* __restrict__ out)
{
    int idx = blockIdx.x*blockDim.x + threadIdx.x;
    if (idx >= MTOT*12) return;
    int m = idx / 12, k = idx % 12;
    int b = m >> 10, s = m & 1023;
    out[(long)b*NCLS*OUTROW + (long)s*OUTROW + NCLS + k] = g_out2[(long)m*DIN + 512 + k];
}

// ---------------- launch ----------------
static inline dim3 gemm_grid(int N) { return dim3((N + 127)/128, MTOT/128); }

extern "C" void kernel_launch(void* const* d_in, const int* in_sizes, int n_in,
                              void* d_out, int out_size)
{
    const float* saml       = (const float*)d_in[0];
    const float* emb_table  = (const float*)d_in[1];
    const float* proj_in_w  = (const float*)d_in[2];
    const float* proj_in_b  = (const float*)d_in[3];
    const float* ga         = (const float*)d_in[4];
    const float* gf         = (const float*)d_in[5];
    const float* Wq         = (const float*)d_in[6];
    const float* Wk         = (const float*)d_in[7];
    const float* Wv         = (const float*)d_in[8];
    const float* Wo         = (const float*)d_in[9];
    const float* bo         = (const float*)d_in[10];
    const float* relpos     = (const float*)d_in[11];
    const float* W1         = (const float*)d_in[12];
    const float* b1         = (const float*)d_in[13];
    const float* W2         = (const float*)d_in[14];
    const float* b2         = (const float*)d_in[15];
    const float* ln_g       = (const float*)d_in[16];
    const float* ln_b       = (const float*)d_in[17];
    const float* proj_out_w = (const float*)d_in[18];
    const float* proj_out_b = (const float*)d_in[19];
    const float* cls_w      = (const float*)d_in[20];
    const float* cls_b      = (const float*)d_in[21];
    float* outp = (float*)d_out;

    float *px, *ph, *phn, *pq, *pk, *pv, *po, *pff, *pout;
    cudaGetSymbolAddress((void**)&px,  g_x);
    cudaGetSymbolAddress((void**)&ph,  g_h);
    cudaGetSymbolAddress((void**)&phn, g_hn);
    cudaGetSymbolAddress((void**)&pq,  g_q);
    cudaGetSymbolAddress((void**)&pk,  g_k);
    cudaGetSymbolAddress((void**)&pv,  g_v);
    cudaGetSymbolAddress((void**)&po,  g_o);
    cudaGetSymbolAddress((void**)&pff, g_ff);
    cudaGetSymbolAddress((void**)&pout,g_out2);

    bias_table_kernel<<<4, 256>>>(relpos);
    embed_kernel<<<MTOT, 256>>>(saml, emb_table);

    // h = x @ proj_in_w + b
    sgemm_kernel<1,false><<<gemm_grid(DMODEL), 256>>>(MTOT, DMODEL, DIN,
        px, DIN, proj_in_w, DMODEL, proj_in_b, nullptr, 0, ph, DMODEL);

    for (int l = 0; l < 6; l++) {
        const float* wq = Wq + (long)l*DMODEL*DMODEL;
        const float* wk = Wk + (long)l*DMODEL*DMODEL;
        const float* wv = Wv + (long)l*DMODEL*DMODEL;
        const float* wo = Wo + (long)l*DMODEL*DMODEL;
        const float* w1 = W1 + (long)l*DMODEL*DFF;
        const float* w2 = W2 + (long)l*DFF*DMODEL;

        scalenorm_kernel<<<MTOT, 256>>>(ph, phn, ga + l);
        sgemm_kernel<0,false><<<gemm_grid(DMODEL), 256>>>(MTOT, DMODEL, DMODEL,
            phn, DMODEL, wq, DMODEL, nullptr, nullptr, 0, pq, DMODEL);
        sgemm_kernel<0,false><<<gemm_grid(DMODEL), 256>>>(MTOT, DMODEL, DMODEL,
            phn, DMODEL, wk, DMODEL, nullptr, nullptr, 0, pk, DMODEL);
        sgemm_kernel<0,false><<<gemm_grid(DMODEL), 256>>>(MTOT, DMODEL, DMODEL,
            phn, DMODEL, wv, DMODEL, nullptr, nullptr, 0, pv, DMODEL);
        rotary_kernel<<<(MTOT*NHEADS*16 + 255)/256, 256>>>(pq, pk);
        flash_attn_kernel<<<dim3(SEQ/64, BATCH*NHEADS), 256>>>(pq, pk, pv, po);
        // h = h + o @ Wo + bo
        sgemm_kernel<2,false><<<gemm_grid(DMODEL), 256>>>(MTOT, DMODEL, DMODEL,
            po, DMODEL, wo, DMODEL, bo + (long)l*DMODEL, ph, DMODEL, ph, DMODEL);
        scalenorm_kernel<<<MTOT, 256>>>(ph, phn, gf + l);
        // ff = gelu(hn @ W1 + b1)
        sgemm_kernel<3,false><<<gemm_grid(DFF), 256>>>(MTOT, DFF, DMODEL,
            phn, DMODEL, w1, DFF, b1 + (long)l*DFF, nullptr, 0, pff, DFF);
        // h = h + ff @ W2 + b2
        sgemm_kernel<2,false><<<gemm_grid(DMODEL), 256>>>(MTOT, DMODEL, DFF,
            pff, DFF, w2, DMODEL, b2 + (long)l*DMODEL, ph, DMODEL, ph, DMODEL);
    }

    layernorm_kernel<<<MTOT, 256>>>(ph, ln_g, ln_b);
    // out = h @ proj_out_w + b
    sgemm_kernel<1,false><<<gemm_grid(DIN), 256>>>(MTOT, DIN, DMODEL,
        ph, DMODEL, proj_out_w, DIN, proj_out_b, nullptr, 0, pout, DIN);
    // classifier logits, stored transposed into d_out
    sgemm_kernel<1,true><<<gemm_grid(NCLS), 256>>>(MTOT, NCLS, DMODEL,
        pout, DIN, cls_w, NCLS, cls_b, nullptr, 0, outp, 0);
    tail_kernel<<<(MTOT*12 + 255)/256, 256>>>(outp);
}

// round 2
// speedup vs baseline: 1.6112x; 1.6112x over previous
#include <cuda_runtime.h>
#include <math.h>
#include <stdint.h>

#define SEQ 1024
#define BATCH 8
#define MTOT (BATCH*SEQ)   // 8192
#define NHEADS 8
#define DHEAD 64
#define DMODEL 512
#define DIN 524
#define DFF 2048
#define NCLS 1024
#define OUTROW 1036

// ---------------- scratch (device globals; no allocation allowed) ----------------
__device__ float g_x [MTOT*DIN];
__device__ float g_h [MTOT*DMODEL];
__device__ float g_hn[MTOT*DMODEL];
__device__ float g_q [MTOT*DMODEL];
__device__ float g_k [MTOT*DMODEL];
__device__ float g_v [MTOT*DMODEL];
__device__ float g_o [MTOT*DMODEL];
__device__ float g_ff[MTOT*DFF];
__device__ float g_out2[MTOT*DIN];
__device__ float g_bias[NHEADS*SEQ];

// ---------------- relpos bias table ----------------
__global__ void bias_table_kernel(const float* __restrict__ relpos)
{
    int n = blockIdx.x * blockDim.x + threadIdx.x;
    if (n >= SEQ) return;
    int bucket;
    if (n < 4) {
        bucket = n;
    } else {
        int vl = 4 + (int)(logf((float)n * 0.25f) * (4.0f / logf(8.0f)));
        bucket = vl < 7 ? vl : 7;
    }
    for (int h = 0; h < NHEADS; h++)
        g_bias[h*SEQ + n] = relpos[bucket*NHEADS + h] * 8.0f;  // * DIM_HEAD**0.5
}

// ---------------- embedding gather + concat ----------------
__global__ __launch_bounds__(256)
void embed_kernel(const float* __restrict__ saml, const float* __restrict__ emb)
{
    int m = blockIdx.x;              // token index 0..8191
    int b = m >> 10, s = m & 1023;
    const float* row = saml + ((long)b*1025 + s)*13;
    int id = (int)row[0];
    float* x = g_x + (long)m*DIN;
    const float* erow = emb + (long)id*512;
    for (int c = threadIdx.x; c < DIN; c += 256)
        x[c] = (c < 512) ? erow[c] : row[c - 511];
}

// ---------------- tf32 helpers ----------------
__device__ __forceinline__ uint32_t f2tf32(float f) {
    uint32_t r;
    asm("cvt.rna.tf32.f32 %0, %1;" : "=r"(r) : "f"(f));
    return r;
}
__device__ __forceinline__ void mma_tf32(float* c,
    uint32_t a0, uint32_t a1, uint32_t a2, uint32_t a3,
    uint32_t b0, uint32_t b1)
{
    asm volatile(
        "mma.sync.aligned.m16n8k8.row.col.f32.tf32.tf32.f32 "
        "{%0,%1,%2,%3}, {%4,%5,%6,%7}, {%8,%9}, {%0,%1,%2,%3};"
        : "+f"(c[0]), "+f"(c[1]), "+f"(c[2]), "+f"(c[3])
        : "r"(a0), "r"(a1), "r"(a2), "r"(a3), "r"(b0), "r"(b1));
}

// ---------------- TF32 tensor-core GEMM: C = op(A@B [+bias] [+Res]) ----------------
// MODE: 0 plain, 1 +bias, 2 +bias+residual, 3 gelu(+bias)
// Block tile 128x128, K-tile 32, 8 warps (2x4), warp tile 64x32.
#define LDA_S 36
#define LDB_S 136
template<int MODE, bool TSTORE>
__global__ __launch_bounds__(256, 2)
void tgemm_kernel(int M, int N, int K,
                  const float* __restrict__ A, int lda,
                  const float* __restrict__ B, int ldb,
                  const float* __restrict__ bias,
                  const float* __restrict__ Res, int ldr,
                  float* __restrict__ C, int ldc)
{
    __shared__ uint32_t As[128*LDA_S];
    __shared__ uint32_t Bs[32*LDB_S];

    const int tid  = threadIdx.x;
    const int wid  = tid >> 5;
    const int lane = tid & 31;
    const int g    = lane >> 2;      // group id 0..7
    const int tg   = lane & 3;       // 0..3
    const int wm   = wid >> 2;       // 0..1
    const int wn   = wid & 3;        // 0..3
    const int row0 = blockIdx.y * 128;
    const int col0 = blockIdx.x * 128;

    float acc[4][4][4];
    #pragma unroll
    for (int mi=0;mi<4;mi++)
        #pragma unroll
        for (int ni=0;ni<4;ni++)
            #pragma unroll
            for (int r=0;r<4;r++) acc[mi][ni][r]=0.f;

    for (int kt = 0; kt < K; kt += 32) {
        // load A tile 128x32 (row0..row0+127, kt..kt+31), convert to tf32
        #pragma unroll
        for (int i = 0; i < 4; i++) {
            int idx = tid + i*256;          // 0..1023 float4 slots
            int r  = idx >> 3;              // 0..127
            int c4 = (idx & 7) * 4;         // 0..28
            int k4 = kt + c4;
            const float* Ap = A + (long)(row0 + r)*lda + k4;
            float4 av;
            if (k4 + 3 < K) av = *(const float4*)Ap;
            else {
                av.x = (k4+0<K)?Ap[0]:0.f;
                av.y = (k4+1<K)?Ap[1]:0.f;
                av.z = (k4+2<K)?Ap[2]:0.f;
                av.w = (k4+3<K)?Ap[3]:0.f;
            }
            uint32_t* dst = &As[r*LDA_S + c4];
            dst[0]=f2tf32(av.x); dst[1]=f2tf32(av.y);
            dst[2]=f2tf32(av.z); dst[3]=f2tf32(av.w);
        }
        // load B tile 32x128 (kt..kt+31, col0..col0+127)
        #pragma unroll
        for (int i = 0; i < 4; i++) {
            int idx = tid + i*256;
            int kk = idx >> 5;              // 0..31
            int n4 = (idx & 31) * 4;        // 0..124
            int k  = kt + kk;
            int c  = col0 + n4;
            float4 bv = make_float4(0.f,0.f,0.f,0.f);
            if (k < K) {
                const float* Bp = B + (long)k*ldb + c;
                if (c + 3 < N) bv = *(const float4*)Bp;
                else {
                    bv.x = (c+0<N)?Bp[0]:0.f;
                    bv.y = (c+1<N)?Bp[1]:0.f;
                    bv.z = (c+2<N)?Bp[2]:0.f;
                    bv.w = (c+3<N)?Bp[3]:0.f;
                }
            }
            uint32_t* dst = &Bs[kk*LDB_S + n4];
            dst[0]=f2tf32(bv.x); dst[1]=f2tf32(bv.y);
            dst[2]=f2tf32(bv.z); dst[3]=f2tf32(bv.w);
        }
        __syncthreads();

        #pragma unroll
        for (int ks = 0; ks < 4; ks++) {
            const int k8 = ks*8;
            uint32_t a[4][4], b[4][2];
            #pragma unroll
            for (int mi=0;mi<4;mi++) {
                int mr = wm*64 + mi*16 + g;
                a[mi][0] = As[(mr  )*LDA_S + k8 + tg];
                a[mi][1] = As[(mr+8)*LDA_S + k8 + tg];
                a[mi][2] = As[(mr  )*LDA_S + k8 + tg + 4];
                a[mi][3] = As[(mr+8)*LDA_S + k8 + tg + 4];
            }
            #pragma unroll
            for (int ni=0;ni<4;ni++) {
                int nc = wn*32 + ni*8 + g;
                b[ni][0] = Bs[(k8+tg  )*LDB_S + nc];
                b[ni][1] = Bs[(k8+tg+4)*LDB_S + nc];
            }
            #pragma unroll
            for (int mi=0;mi<4;mi++)
                #pragma unroll
                for (int ni=0;ni<4;ni++)
                    mma_tf32(acc[mi][ni], a[mi][0],a[mi][1],a[mi][2],a[mi][3],
                             b[ni][0], b[ni][1]);
        }
        __syncthreads();
    }

    // epilogue
    #pragma unroll
    for (int mi=0;mi<4;mi++) {
        #pragma unroll
        for (int ni=0;ni<4;ni++) {
            #pragma unroll
            for (int r=0;r<4;r++) {
                int row = row0 + wm*64 + mi*16 + g + ((r>=2)?8:0);
                int col = col0 + wn*32 + ni*8 + tg*2 + (r&1);
                if (col < N) {
                    float v = acc[mi][ni][r];
                    if (MODE >= 1) v += bias[col];
                    if (MODE == 2) v += Res[(long)row*ldr + col];
                    if (MODE == 3) v = 0.5f*v*(1.f + erff(v*0.7071067811865476f));
                    if (TSTORE) {
                        int b_ = row >> 10, s_ = row & 1023;
                        C[(long)b_*(NCLS*OUTROW) + (long)col*OUTROW + s_] = v;
                    } else {
                        C[(long)row*ldc + col] = v;
                    }
                }
            }
        }
    }
}

// ---------------- scalenorm ----------------
__global__ __launch_bounds__(256)
void scalenorm_kernel(const float* __restrict__ X, float* __restrict__ Y,
                      const float* __restrict__ gptr)
{
    int m = blockIdx.x;
    const float* x = X + (long)m*DMODEL;
    int t = threadIdx.x;
    float v0 = x[t], v1 = x[t+256];
    float ss = v0*v0 + v1*v1;
    #pragma unroll
    for (int off=16; off; off>>=1) ss += __shfl_xor_sync(0xffffffffu, ss, off);
    __shared__ float red[8];
    if ((t & 31) == 0) red[t>>5] = ss;
    __syncthreads();
    __shared__ float tot;
    if (t < 32) {
        float s2 = (t < 8) ? red[t] : 0.f;
        #pragma unroll
        for (int off=4; off; off>>=1) s2 += __shfl_xor_sync(0xffffffffu, s2, off);
        if (t == 0) tot = s2;
    }
    __syncthreads();
    float n = sqrtf(tot) * 0.04419417382415922f;   // * 512^-0.5
    float f = gptr[0] / fmaxf(n, 1e-5f);
    float* y = Y + (long)m*DMODEL;
    y[t] = v0*f; y[t+256] = v1*f;
}

// ---------------- final layernorm (in place) ----------------
__global__ __launch_bounds__(256)
void layernorm_kernel(float* __restrict__ X,
                      const float* __restrict__ gam, const float* __restrict__ bet)
{
    int m = blockIdx.x;
    float* x = X + (long)m*DMODEL;
    int t = threadIdx.x;
    float v0 = x[t], v1 = x[t+256];
    float s1 = v0 + v1, s2 = v0*v0 + v1*v1;
    #pragma unroll
    for (int off=16; off; off>>=1) {
        s1 += __shfl_xor_sync(0xffffffffu, s1, off);
        s2 += __shfl_xor_sync(0xffffffffu, s2, off);
    }
    __shared__ float r1[8], r2[8];
    if ((t & 31) == 0) { r1[t>>5]=s1; r2[t>>5]=s2; }
    __syncthreads();
    __shared__ float mu_s, rs_s;
    if (t < 32) {
        float a = (t<8)?r1[t]:0.f, b = (t<8)?r2[t]:0.f;
        #pragma unroll
        for (int off=4; off; off>>=1) {
            a += __shfl_xor_sync(0xffffffffu, a, off);
            b += __shfl_xor_sync(0xffffffffu, b, off);
        }
        if (t == 0) {
            float mu = a * (1.f/512.f);
            float var = b * (1.f/512.f) - mu*mu;
            mu_s = mu; rs_s = rsqrtf(var + 1e-5f);
        }
    }
    __syncthreads();
    float mu = mu_s, rs = rs_s;
    x[t]     = (v0 - mu)*rs*gam[t]     + bet[t];
    x[t+256] = (v1 - mu)*rs*gam[t+256] + bet[t+256];
}

// ---------------- rotary on q,k (first 32 dims of each head) ----------------
__global__ __launch_bounds__(256)
void rotary_kernel(float* __restrict__ Q, float* __restrict__ Kg)
{
    int idx = blockIdx.x*blockDim.x + threadIdx.x;
    if (idx >= MTOT*NHEADS*16) return;
    int d    = idx & 15;
    int head = (idx >> 4) & 7;
    int m    = idx >> 7;
    int s    = m & 1023;
    float inv = expf(-(float)(2*d) * (9.210340371976184f/32.f));  // 10000^(-2d/32)
    float ang = (float)s * inv;
    float sn, c;
    sincosf(ang, &sn, &c);
    long base = (long)m*DMODEL + head*DHEAD + d;
    float a = Q[base], b = Q[base+16];
    Q[base]    = a*c - b*sn;
    Q[base+16] = b*c + a*sn;
    a = Kg[base]; b = Kg[base+16];
    Kg[base]    = a*c - b*sn;
    Kg[base+16] = b*c + a*sn;
}

// ---------------- flash attention (64x64 tiles, online softmax) ----------------
__global__ __launch_bounds__(256)
void flash_attn_kernel(const float* __restrict__ Q, const float* __restrict__ Kg,
                       const float* __restrict__ Vg, float* __restrict__ O)
{
    __shared__ float Qs[64*64];
    __shared__ float KPs[64*64];   // K tile, later reused for P tile (rotation swizzle)
    __shared__ float Vs[64*64];

    const int tid  = threadIdx.x;
    const int qb   = blockIdx.x;          // 0..15
    const int bh   = blockIdx.y;          // 0..63
    const int b    = bh >> 3, head = bh & 7;
    const int q0   = qb * 64;
    const long base = ((long)b * SEQ) * DMODEL + head * DHEAD;

    const int ty = tid >> 4, tx = tid & 15;
    const int r0 = ty * 4;
    const int c0 = tx * 4;

    for (int idx = tid; idx < 64*16; idx += 256) {
        int rr = idx >> 4, c4 = (idx & 15) * 4;
        float4 v = *(const float4*)(Q + base + (long)(q0+rr)*DMODEL + c4);
        Qs[rr*64+c4+0]=v.x; Qs[rr*64+c4+1]=v.y; Qs[rr*64+c4+2]=v.z; Qs[rr*64+c4+3]=v.w;
    }

    float m_run[4], l_run[4], o[4][4];
    #pragma unroll
    for (int i=0;i<4;i++){ m_run[i]=-3.0e38f; l_run[i]=0.f;
        #pragma unroll
        for (int j=0;j<4;j++) o[i][j]=0.f; }

    for (int kt = 0; kt <= qb; kt++) {
        int k0 = kt * 64;
        __syncthreads();
        for (int idx = tid; idx < 64*16; idx += 256) {
            int jj = idx >> 4, c4 = (idx & 15) * 4;
            float4 kv = *(const float4*)(Kg + base + (long)(k0+jj)*DMODEL + c4);
            KPs[jj*64 + ((c4+0+jj)&63)] = kv.x;
            KPs[jj*64 + ((c4+1+jj)&63)] = kv.y;
            KPs[jj*64 + ((c4+2+jj)&63)] = kv.z;
            KPs[jj*64 + ((c4+3+jj)&63)] = kv.w;
            float4 vv = *(const float4*)(Vg + base + (long)(k0+jj)*DMODEL + c4);
            *(float4*)(&Vs[jj*64 + c4]) = vv;
        }
        __syncthreads();

        float s[4][4];
        #pragma unroll
        for (int i=0;i<4;i++)
            #pragma unroll
            for (int j=0;j<4;j++) s[i][j]=0.f;
        for (int kk = 0; kk < 64; kk++) {
            float qv[4], kv[4];
            #pragma unroll
            for (int i=0;i<4;i++) qv[i] = Qs[(r0+i)*64 + kk];
            #pragma unroll
            for (int j=0;j<4;j++) kv[j] = KPs[(c0+j)*64 + ((kk + c0 + j)&63)];
            #pragma unroll
            for (int i=0;i<4;i++)
                #pragma unroll
                for (int j=0;j<4;j++)
                    s[i][j] = fmaf(qv[i], kv[j], s[i][j]);
        }
        #pragma unroll
        for (int i=0;i<4;i++) {
            int qi = q0 + r0 + i;
            #pragma unroll
            for (int j=0;j<4;j++) {
                int kj = k0 + c0 + j;
                if (kj > qi) s[i][j] = -3.0e38f;
                else         s[i][j] = s[i][j]*0.125f + g_bias[head*SEQ + (qi - kj)];
            }
        }
        #pragma unroll
        for (int i=0;i<4;i++) {
            float mx = fmaxf(fmaxf(s[i][0],s[i][1]),fmaxf(s[i][2],s[i][3]));
            mx = fmaxf(mx, __shfl_xor_sync(0xffffffffu, mx, 8));
            mx = fmaxf(mx, __shfl_xor_sync(0xffffffffu, mx, 4));
            mx = fmaxf(mx, __shfl_xor_sync(0xffffffffu, mx, 2));
            mx = fmaxf(mx, __shfl_xor_sync(0xffffffffu, mx, 1));
            float m_new = fmaxf(m_run[i], mx);
            float alpha = __expf(m_run[i] - m_new);
            float ls = 0.f;
            #pragma unroll
            for (int j=0;j<4;j++) { s[i][j] = __expf(s[i][j] - m_new); ls += s[i][j]; }
            ls += __shfl_xor_sync(0xffffffffu, ls, 8);
            ls += __shfl_xor_sync(0xffffffffu, ls, 4);
            ls += __shfl_xor_sync(0xffffffffu, ls, 2);
            ls += __shfl_xor_sync(0xffffffffu, ls, 1);
            l_run[i] = l_run[i]*alpha + ls;
            m_run[i] = m_new;
            #pragma unroll
            for (int j=0;j<4;j++) o[i][j] *= alpha;
        }
        __syncthreads();
        #pragma unroll
        for (int i=0;i<4;i++){
            int r = r0 + i;
            #pragma unroll
            for (int j=0;j<4;j++)
                KPs[r*64 + ((c0+j+r)&63)] = s[i][j];
        }
        __syncthreads();
        for (int jj = 0; jj < 64; jj++) {
            float pv[4], vv[4];
            #pragma unroll
            for (int i=0;i<4;i++) pv[i] = KPs[(r0+i)*64 + ((jj + r0 + i)&63)];
            #pragma unroll
            for (int j=0;j<4;j++) vv[j] = Vs[jj*64 + c0 + j];
            #pragma unroll
            for (int i=0;i<4;i++)
                #pragma unroll
                for (int j=0;j<4;j++)
                    o[i][j] = fmaf(pv[i], vv[j], o[i][j]);
        }
    }
    #pragma unroll
    for (int i=0;i<4;i++){
        float inv_l = 1.f / l_run[i];
        #pragma unroll
        for (int j=0;j<4;j++)
            O[base + (long)(q0 + r0 + i)*DMODEL + c0 + j] = o[i][j]*inv_l;
    }
}

// ---------------- tail copy (last 12 output columns) ----------------
__global__ void tail_kernel(float* __restrict__ out)
{
    int idx = blockIdx.x*blockDim.x + threadIdx.x;
    if (idx >= MTOT*12) return;
    int m = idx / 12, k = idx % 12;
    int b = m >> 10, s = m & 1023;
    out[(long)b*NCLS*OUTROW + (long)s*OUTROW + NCLS + k] = g_out2[(long)m*DIN + 512 + k];
}

// ---------------- launch ----------------
static inline dim3 gemm_grid(int N) { return dim3((N + 127)/128, MTOT/128); }

extern "C" void kernel_launch(void* const* d_in, const int* in_sizes, int n_in,
                              void* d_out, int out_size)
{
    const float* saml       = (const float*)d_in[0];
    const float* emb_table  = (const float*)d_in[1];
    const float* proj_in_w  = (const float*)d_in[2];
    const float* proj_in_b  = (const float*)d_in[3];
    const float* ga         = (const float*)d_in[4];
    const float* gf         = (const float*)d_in[5];
    const float* Wq         = (const float*)d_in[6];
    const float* Wk         = (const float*)d_in[7];
    const float* Wv         = (const float*)d_in[8];
    const float* Wo         = (const float*)d_in[9];
    const float* bo         = (const float*)d_in[10];
    const float* relpos     = (const float*)d_in[11];
    const float* W1         = (const float*)d_in[12];
    const float* b1         = (const float*)d_in[13];
    const float* W2         = (const float*)d_in[14];
    const float* b2         = (const float*)d_in[15];
    const float* ln_g       = (const float*)d_in[16];
    const float* ln_b       = (const float*)d_in[17];
    const float* proj_out_w = (const float*)d_in[18];
    const float* proj_out_b = (const float*)d_in[19];
    const float* cls_w      = (const float*)d_in[20];
    const float* cls_b      = (const float*)d_in[21];
    float* outp = (float*)d_out;

    float *px, *ph, *phn, *pq, *pk, *pv, *po, *pff, *pout;
    cudaGetSymbolAddress((void**)&px,  g_x);
    cudaGetSymbolAddress((void**)&ph,  g_h);
    cudaGetSymbolAddress((void**)&phn, g_hn);
    cudaGetSymbolAddress((void**)&pq,  g_q);
    cudaGetSymbolAddress((void**)&pk,  g_k);
    cudaGetSymbolAddress((void**)&pv,  g_v);
    cudaGetSymbolAddress((void**)&po,  g_o);
    cudaGetSymbolAddress((void**)&pff, g_ff);
    cudaGetSymbolAddress((void**)&pout,g_out2);

    bias_table_kernel<<<4, 256>>>(relpos);
    embed_kernel<<<MTOT, 256>>>(saml, emb_table);

    // h = x @ proj_in_w + b
    tgemm_kernel<1,false><<<gemm_grid(DMODEL), 256>>>(MTOT, DMODEL, DIN,
        px, DIN, proj_in_w, DMODEL, proj_in_b, nullptr, 0, ph, DMODEL);

    for (int l = 0; l < 6; l++) {
        const float* wq = Wq + (long)l*DMODEL*DMODEL;
        const float* wk = Wk + (long)l*DMODEL*DMODEL;
        const float* wv = Wv + (long)l*DMODEL*DMODEL;
        const float* wo = Wo + (long)l*DMODEL*DMODEL;
        const float* w1 = W1 + (long)l*DMODEL*DFF;
        const float* w2 = W2 + (long)l*DFF*DMODEL;

        scalenorm_kernel<<<MTOT, 256>>>(ph, phn, ga + l);
        tgemm_kernel<0,false><<<gemm_grid(DMODEL), 256>>>(MTOT, DMODEL, DMODEL,
            phn, DMODEL, wq, DMODEL, nullptr, nullptr, 0, pq, DMODEL);
        tgemm_kernel<0,false><<<gemm_grid(DMODEL), 256>>>(MTOT, DMODEL, DMODEL,
            phn, DMODEL, wk, DMODEL, nullptr, nullptr, 0, pk, DMODEL);
        tgemm_kernel<0,false><<<gemm_grid(DMODEL), 256>>>(MTOT, DMODEL, DMODEL,
            phn, DMODEL, wv, DMODEL, nullptr, nullptr, 0, pv, DMODEL);
        rotary_kernel<<<(MTOT*NHEADS*16 + 255)/256, 256>>>(pq, pk);
        flash_attn_kernel<<<dim3(SEQ/64, BATCH*NHEADS), 256>>>(pq, pk, pv, po);
        // h = h + o @ Wo + bo
        tgemm_kernel<2,false><<<gemm_grid(DMODEL), 256>>>(MTOT, DMODEL, DMODEL,
            po, DMODEL, wo, DMODEL, bo + (long)l*DMODEL, ph, DMODEL, ph, DMODEL);
        scalenorm_kernel<<<MTOT, 256>>>(ph, phn, gf + l);
        // ff = gelu(hn @ W1 + b1)
        tgemm_kernel<3,false><<<gemm_grid(DFF), 256>>>(MTOT, DFF, DMODEL,
            phn, DMODEL, w1, DFF, b1 + (long)l*DFF, nullptr, 0, pff, DFF);
        // h = h + ff @ W2 + b2
        tgemm_kernel<2,false><<<gemm_grid(DMODEL), 256>>>(MTOT, DMODEL, DFF,
            pff, DFF, w2, DMODEL, b2 + (long)l*DMODEL, ph, DMODEL, ph, DMODEL);
    }

    layernorm_kernel<<<MTOT, 256>>>(ph, ln_g, ln_b);
    // out = h @ proj_out_w + b
    tgemm_kernel<1,false><<<gemm_grid(DIN), 256>>>(MTOT, DIN, DMODEL,
        ph, DMODEL, proj_out_w, DIN, proj_out_b, nullptr, 0, pout, DIN);
    // classifier logits, stored transposed into d_out
    tgemm_kernel<1,true><<<gemm_grid(NCLS), 256>>>(MTOT, NCLS, DMODEL,
        pout, DIN, cls_w, NCLS, cls_b, nullptr, 0, outp, 0);
    tail_kernel<<<(MTOT*12 + 255)/256, 256>>>(outp);
}

// round 3
// speedup vs baseline: 2.7849x; 1.7285x over previous
#include <cuda_runtime.h>
#include <math.h>
#include <stdint.h>

#define SEQ 1024
#define BATCH 8
#define MTOT (BATCH*SEQ)   // 8192
#define NHEADS 8
#define DHEAD 64
#define DMODEL 512
#define DIN 524
#define DFF 2048
#define NCLS 1024
#define OUTROW 1036

// ---------------- scratch (device globals; no allocation allowed) ----------------
__device__ float g_x [MTOT*DIN];
__device__ float g_h [MTOT*DMODEL];
__device__ float g_hn[MTOT*DMODEL];
__device__ float g_q [MTOT*DMODEL];
__device__ float g_k [MTOT*DMODEL];
__device__ float g_v [MTOT*DMODEL];
__device__ float g_o [MTOT*DMODEL];
__device__ float g_ff[MTOT*DFF];
__device__ float g_out2[MTOT*DIN];
__device__ float g_bias[NHEADS*SEQ];

// ---------------- relpos bias table ----------------
__global__ void bias_table_kernel(const float* __restrict__ relpos)
{
    int n = blockIdx.x * blockDim.x + threadIdx.x;
    if (n >= SEQ) return;
    int bucket;
    if (n < 4) {
        bucket = n;
    } else {
        int vl = 4 + (int)(logf((float)n * 0.25f) * (4.0f / logf(8.0f)));
        bucket = vl < 7 ? vl : 7;
    }
    for (int h = 0; h < NHEADS; h++)
        g_bias[h*SEQ + n] = relpos[bucket*NHEADS + h] * 8.0f;  // * DIM_HEAD**0.5
}

// ---------------- embedding gather + concat ----------------
__global__ __launch_bounds__(256)
void embed_kernel(const float* __restrict__ saml, const float* __restrict__ emb)
{
    int m = blockIdx.x;              // token index 0..8191
    int b = m >> 10, s = m & 1023;
    const float* row = saml + ((long)b*1025 + s)*13;
    int id = (int)row[0];
    float* x = g_x + (long)m*DIN;
    const float* erow = emb + (long)id*512;
    for (int c = threadIdx.x; c < DIN; c += 256)
        x[c] = (c < 512) ? erow[c] : row[c - 511];
}

// ---------------- tf32 helpers ----------------
__device__ __forceinline__ uint32_t f2tf32(float f) {
    uint32_t r;
    asm("cvt.rna.tf32.f32 %0, %1;" : "=r"(r) : "f"(f));
    return r;
}
__device__ __forceinline__ void mma_tf32(float* c,
    uint32_t a0, uint32_t a1, uint32_t a2, uint32_t a3,
    uint32_t b0, uint32_t b1)
{
    asm volatile(
        "mma.sync.aligned.m16n8k8.row.col.f32.tf32.tf32.f32 "
        "{%0,%1,%2,%3}, {%4,%5,%6,%7}, {%8,%9}, {%0,%1,%2,%3};"
        : "+f"(c[0]), "+f"(c[1]), "+f"(c[2]), "+f"(c[3])
        : "r"(a0), "r"(a1), "r"(a2), "r"(a3), "r"(b0), "r"(b1));
}
__device__ __forceinline__ void cp_async16(float* dst, const float* src, bool pred) {
    uint32_t d = (uint32_t)__cvta_generic_to_shared(dst);
    int bytes = pred ? 16 : 0;
    asm volatile("cp.async.cg.shared.global [%0], [%1], 16, %2;\n"
                 :: "r"(d), "l"(src), "r"(bytes));
}
__device__ __forceinline__ void cp_commit() {
    asm volatile("cp.async.commit_group;\n" ::);
}
template<int N>
__device__ __forceinline__ void cp_wait() {
    asm volatile("cp.async.wait_group %0;\n" :: "n"(N));
}

// ---------------- TF32 tensor-core GEMM ----------------
#define LDA_S 36
#define LDB_S 136
#define ASTG (128*LDA_S)
#define BSTG (32*LDB_S)
#define GEMM_SMEM ((2*(ASTG+BSTG))*4)

template<int MODE, bool TSTORE>
__global__ __launch_bounds__(256)
void tgemm_kernel(int M, int N, int K,
                  const float* __restrict__ A, int lda,
                  const float* __restrict__ B, int ldb,
                  const float* __restrict__ bias,
                  const float* __restrict__ Res, int ldr,
                  float* __restrict__ C, int ldc)
{
    extern __shared__ float sm[];
    float* As = sm;
    float* Bs = sm + 2*ASTG;

    const int tid  = threadIdx.x;
    const int wid  = tid >> 5;
    const int lane = tid & 31;
    const int g    = lane >> 2;
    const int tg   = lane & 3;
    const int wm   = wid >> 2;
    const int wn   = wid & 3;
    const int row0 = blockIdx.y * 128;
    const int col0 = blockIdx.x * 128;

    float acc[4][4][4];
    #pragma unroll
    for (int mi=0;mi<4;mi++)
        #pragma unroll
        for (int ni=0;ni<4;ni++)
            #pragma unroll
            for (int r=0;r<4;r++) acc[mi][ni][r]=0.f;

    const int nt = (K + 31) / 32;

#define LOAD_TILE(STG, KT)                                                        \
    {                                                                             \
        _Pragma("unroll")                                                         \
        for (int i = 0; i < 4; i++) {                                             \
            int idx = tid + i*256;                                                \
            int r  = idx >> 3;                                                    \
            int c4 = (idx & 7) * 4;                                               \
            int k4 = (KT) + c4;                                                   \
            bool p = (k4 < K);                                                    \
            const float* src = A + (long)(row0 + r)*lda + (p ? k4 : 0);           \
            cp_async16(As + (STG)*ASTG + r*LDA_S + c4, src, p);                   \
        }                                                                         \
        _Pragma("unroll")                                                         \
        for (int i = 0; i < 4; i++) {                                             \
            int idx = tid + i*256;                                                \
            int kk = idx >> 5;                                                    \
            int n4 = (idx & 31) * 4;                                              \
            int k  = (KT) + kk;                                                   \
            int c  = col0 + n4;                                                   \
            bool p = (k < K) && (c < N);                                          \
            const float* src = B + (long)(p ? k : 0)*ldb + (p ? c : 0);           \
            cp_async16(Bs + (STG)*BSTG + kk*LDB_S + n4, src, p);                  \
        }                                                                         \
        cp_commit();                                                              \
    }

    LOAD_TILE(0, 0)

    for (int t = 0; t < nt; t++) {
        if (t + 1 < nt) {
            LOAD_TILE((t+1)&1, (t+1)*32)
            cp_wait<1>();
        } else {
            cp_wait<0>();
        }
        __syncthreads();

        const float* Ac = As + (t&1)*ASTG;
        const float* Bc = Bs + (t&1)*BSTG;
        #pragma unroll
        for (int ks = 0; ks < 4; ks++) {
            const int k8 = ks*8;
            uint32_t a[4][4], b[4][2];
            #pragma unroll
            for (int mi=0;mi<4;mi++) {
                int mr = wm*64 + mi*16 + g;
                a[mi][0] = f2tf32(Ac[(mr  )*LDA_S + k8 + tg]);
                a[mi][1] = f2tf32(Ac[(mr+8)*LDA_S + k8 + tg]);
                a[mi][2] = f2tf32(Ac[(mr  )*LDA_S + k8 + tg + 4]);
                a[mi][3] = f2tf32(Ac[(mr+8)*LDA_S + k8 + tg + 4]);
            }
            #pragma unroll
            for (int ni=0;ni<4;ni++) {
                int nc = wn*32 + ni*8 + g;
                b[ni][0] = f2tf32(Bc[(k8+tg  )*LDB_S + nc]);
                b[ni][1] = f2tf32(Bc[(k8+tg+4)*LDB_S + nc]);
            }
            #pragma unroll
            for (int mi=0;mi<4;mi++)
                #pragma unroll
                for (int ni=0;ni<4;ni++)
                    mma_tf32(acc[mi][ni], a[mi][0],a[mi][1],a[mi][2],a[mi][3],
                             b[ni][0], b[ni][1]);
        }
        __syncthreads();
    }

    #pragma unroll
    for (int mi=0;mi<4;mi++) {
        #pragma unroll
        for (int ni=0;ni<4;ni++) {
            #pragma unroll
            for (int r=0;r<4;r++) {
                int row = row0 + wm*64 + mi*16 + g + ((r>=2)?8:0);
                int col = col0 + wn*32 + ni*8 + tg*2 + (r&1);
                if (col < N) {
                    float v = acc[mi][ni][r];
                    if (MODE >= 1) v += bias[col];
                    if (MODE == 2) v += Res[(long)row*ldr + col];
                    if (MODE == 3) v = 0.5f*v*(1.f + erff(v*0.7071067811865476f));
                    if (TSTORE) {
                        int b_ = row >> 10, s_ = row & 1023;
                        C[(long)b_*(NCLS*OUTROW) + (long)col*OUTROW + s_] = v;
                    } else {
                        C[(long)row*ldc + col] = v;
                    }
                }
            }
        }
    }
}

// ---------------- scalenorm ----------------
__global__ __launch_bounds__(256)
void scalenorm_kernel(const float* __restrict__ X, float* __restrict__ Y,
                      const float* __restrict__ gptr)
{
    int m = blockIdx.x;
    const float* x = X + (long)m*DMODEL;
    int t = threadIdx.x;
    float v0 = x[t], v1 = x[t+256];
    float ss = v0*v0 + v1*v1;
    #pragma unroll
    for (int off=16; off; off>>=1) ss += __shfl_xor_sync(0xffffffffu, ss, off);
    __shared__ float red[8];
    if ((t & 31) == 0) red[t>>5] = ss;
    __syncthreads();
    __shared__ float tot;
    if (t < 32) {
        float s2 = (t < 8) ? red[t] : 0.f;
        #pragma unroll
        for (int off=4; off; off>>=1) s2 += __shfl_xor_sync(0xffffffffu, s2, off);
        if (t == 0) tot = s2;
    }
    __syncthreads();
    float n = sqrtf(tot) * 0.04419417382415922f;
    float f = gptr[0] / fmaxf(n, 1e-5f);
    float* y = Y + (long)m*DMODEL;
    y[t] = v0*f; y[t+256] = v1*f;
}

// ---------------- final layernorm (in place) ----------------
__global__ __launch_bounds__(256)
void layernorm_kernel(float* __restrict__ X,
                      const float* __restrict__ gam, const float* __restrict__ bet)
{
    int m = blockIdx.x;
    float* x = X + (long)m*DMODEL;
    int t = threadIdx.x;
    float v0 = x[t], v1 = x[t+256];
    float s1 = v0 + v1, s2 = v0*v0 + v1*v1;
    #pragma unroll
    for (int off=16; off; off>>=1) {
        s1 += __shfl_xor_sync(0xffffffffu, s1, off);
        s2 += __shfl_xor_sync(0xffffffffu, s2, off);
    }
    __shared__ float r1[8], r2[8];
    if ((t & 31) == 0) { r1[t>>5]=s1; r2[t>>5]=s2; }
    __syncthreads();
    __shared__ float mu_s, rs_s;
    if (t < 32) {
        float a = (t<8)?r1[t]:0.f, b = (t<8)?r2[t]:0.f;
        #pragma unroll
        for (int off=4; off; off>>=1) {
            a += __shfl_xor_sync(0xffffffffu, a, off);
            b += __shfl_xor_sync(0xffffffffu, b, off);
        }
        if (t == 0) {
            float mu = a * (1.f/512.f);
            float var = b * (1.f/512.f) - mu*mu;
            mu_s = mu; rs_s = rsqrtf(var + 1e-5f);
        }
    }
    __syncthreads();
    float mu = mu_s, rs = rs_s;
    x[t]     = (v0 - mu)*rs*gam[t]     + bet[t];
    x[t+256] = (v1 - mu)*rs*gam[t+256] + bet[t+256];
}

// ---------------- rotary on q,k ----------------
__global__ __launch_bounds__(256)
void rotary_kernel(float* __restrict__ Q, float* __restrict__ Kg)
{
    int idx = blockIdx.x*blockDim.x + threadIdx.x;
    if (idx >= MTOT*NHEADS*16) return;
    int d    = idx & 15;
    int head = (idx >> 4) & 7;
    int m    = idx >> 7;
    int s    = m & 1023;
    float inv = expf(-(float)(2*d) * (9.210340371976184f/32.f));
    float ang = (float)s * inv;
    float sn, c;
    sincosf(ang, &sn, &c);
    long base = (long)m*DMODEL + head*DHEAD + d;
    float a = Q[base], b = Q[base+16];
    Q[base]    = a*c - b*sn;
    Q[base+16] = b*c + a*sn;
    a = Kg[base]; b = Kg[base+16];
    Kg[base]    = a*c - b*sn;
    Kg[base+16] = b*c + a*sn;
}

// ---------------- flash attention (float4 + XOR swizzle) ----------------
#define FLASH_SMEM ((3*4096 + 1024)*4)
__global__ __launch_bounds__(256)
void flash_attn_kernel(const float* __restrict__ Q, const float* __restrict__ Kg,
                       const float* __restrict__ Vg, float* __restrict__ O)
{
    extern __shared__ float fsm[];
    float* Qs = fsm;
    float* Ks = fsm + 4096;
    float* Vs = fsm + 8192;
    float* bs = fsm + 12288;

    const int tid  = threadIdx.x;
    const int qb   = blockIdx.x;
    const int bh   = blockIdx.y;
    const int b    = bh >> 3, head = bh & 7;
    const int q0   = qb * 64;
    const long base = ((long)b * SEQ) * DMODEL + head * DHEAD;

    const int ty = tid >> 4, tx = tid & 15;
    const int r0 = ty * 4;
    const int c0 = tx * 4;

    for (int i = tid; i < SEQ; i += 256) bs[i] = g_bias[head*SEQ + i];

    #pragma unroll
    for (int i = 0; i < 4; i++) {
        int idx = tid + i*256;
        int rr = idx >> 4, ss = idx & 15;
        float4 v = *(const float4*)(Q + base + (long)(q0+rr)*DMODEL + ss*4);
        *(float4*)&Qs[rr*64 + ((ss ^ (rr>>2)) << 2)] = v;
    }

    float m_run[4], l_run[4], o[4][4];
    #pragma unroll
    for (int i=0;i<4;i++){ m_run[i]=-3.0e38f; l_run[i]=0.f;
        #pragma unroll
        for (int j=0;j<4;j++) o[i][j]=0.f; }

    for (int kt = 0; kt <= qb; kt++) {
        int k0 = kt * 64;
        __syncthreads();
        #pragma unroll
        for (int i = 0; i < 4; i++) {
            int idx = tid + i*256;
            int rr = idx >> 4, ss = idx & 15;
            int sw = ((ss ^ (rr>>2)) << 2);
            float4 kv = *(const float4*)(Kg + base + (long)(k0+rr)*DMODEL + ss*4);
            *(float4*)&Ks[rr*64 + sw] = kv;
            float4 vv = *(const float4*)(Vg + base + (long)(k0+rr)*DMODEL + ss*4);
            *(float4*)&Vs[rr*64 + sw] = vv;
        }
        __syncthreads();

        float s[4][4];
        #pragma unroll
        for (int i=0;i<4;i++)
            #pragma unroll
            for (int j=0;j<4;j++) s[i][j]=0.f;

        #pragma unroll
        for (int kk4 = 0; kk4 < 16; kk4++) {
            float4 q[4], k[4];
            #pragma unroll
            for (int i=0;i<4;i++) q[i] = *(const float4*)&Qs[(r0+i)*64 + ((kk4 ^ ty) << 2)];
            #pragma unroll
            for (int j=0;j<4;j++) k[j] = *(const float4*)&Ks[(c0+j)*64 + ((kk4 ^ tx) << 2)];
            #pragma unroll
            for (int i=0;i<4;i++)
                #pragma unroll
                for (int j=0;j<4;j++) {
                    s[i][j] = fmaf(q[i].x, k[j].x, s[i][j]);
                    s[i][j] = fmaf(q[i].y, k[j].y, s[i][j]);
                    s[i][j] = fmaf(q[i].z, k[j].z, s[i][j]);
                    s[i][j] = fmaf(q[i].w, k[j].w, s[i][j]);
                }
        }

        #pragma unroll
        for (int i=0;i<4;i++) {
            int qi = q0 + r0 + i;
            #pragma unroll
            for (int j=0;j<4;j++) {
                int kj = k0 + c0 + j;
                if (kj > qi) s[i][j] = -3.0e38f;
                else         s[i][j] = s[i][j]*0.125f + bs[qi - kj];
            }
        }
        #pragma unroll
        for (int i=0;i<4;i++) {
            float mx = fmaxf(fmaxf(s[i][0],s[i][1]),fmaxf(s[i][2],s[i][3]));
            mx = fmaxf(mx, __shfl_xor_sync(0xffffffffu, mx, 8));
            mx = fmaxf(mx, __shfl_xor_sync(0xffffffffu, mx, 4));
            mx = fmaxf(mx, __shfl_xor_sync(0xffffffffu, mx, 2));
            mx = fmaxf(mx, __shfl_xor_sync(0xffffffffu, mx, 1));
            float m_new = fmaxf(m_run[i], mx);
            float alpha = __expf(m_run[i] - m_new);
            float ls = 0.f;
            #pragma unroll
            for (int j=0;j<4;j++) { s[i][j] = __expf(s[i][j] - m_new); ls += s[i][j]; }
            ls += __shfl_xor_sync(0xffffffffu, ls, 8);
            ls += __shfl_xor_sync(0xffffffffu, ls, 4);
            ls += __shfl_xor_sync(0xffffffffu, ls, 2);
            ls += __shfl_xor_sync(0xffffffffu, ls, 1);
            l_run[i] = l_run[i]*alpha + ls;
            m_run[i] = m_new;
            #pragma unroll
            for (int j=0;j<4;j++) o[i][j] *= alpha;
        }
        __syncthreads();
        #pragma unroll
        for (int i=0;i<4;i++)
            *(float4*)&Ks[(r0+i)*64 + ((tx ^ ty) << 2)] =
                make_float4(s[i][0], s[i][1], s[i][2], s[i][3]);
        __syncthreads();

        #pragma unroll
        for (int jj4 = 0; jj4 < 16; jj4++) {
            float4 p[4], v[4];
            #pragma unroll
            for (int i=0;i<4;i++) p[i] = *(const float4*)&Ks[(r0+i)*64 + ((jj4 ^ ty) << 2)];
            #pragma unroll
            for (int u=0;u<4;u++) v[u] = *(const float4*)&Vs[(4*jj4+u)*64 + ((tx ^ jj4) << 2)];
            #pragma unroll
            for (int i=0;i<4;i++) {
                float pc[4] = {p[i].x, p[i].y, p[i].z, p[i].w};
                #pragma unroll
                for (int u=0;u<4;u++) {
                    o[i][0] = fmaf(pc[u], v[u].x, o[i][0]);
                    o[i][1] = fmaf(pc[u], v[u].y, o[i][1]);
                    o[i][2] = fmaf(pc[u], v[u].z, o[i][2]);
                    o[i][3] = fmaf(pc[u], v[u].w, o[i][3]);
                }
            }
        }
    }
    #pragma unroll
    for (int i=0;i<4;i++){
        float inv_l = 1.f / l_run[i];
        #pragma unroll
        for (int j=0;j<4;j++)
            O[base + (long)(q0 + r0 + i)*DMODEL + c0 + j] = o[i][j]*inv_l;
    }
}

// ---------------- tail copy ----------------
__global__ void tail_kernel(float* __restrict__ out)
{
    int idx = blockIdx.x*blockDim.x + threadIdx.x;
    if (idx >= MTOT*12) return;
    int m = idx / 12, k = idx % 12;
    int b = m >> 10, s = m & 1023;
    out[(long)b*NCLS*OUTROW + (long)s*OUTROW + NCLS + k] = g_out2[(long)m*DIN + 512 + k];
}

// ---------------- launch ----------------
static inline dim3 gemm_grid(int N) { return dim3((N + 127)/128, MTOT/128); }

extern "C" void kernel_launch(void* const* d_in, const int* in_sizes, int n_in,
                              void* d_out, int out_size)
{
    const float* saml       = (const float*)d_in[0];
    const float* emb_table  = (const float*)d_in[1];
    const float* proj_in_w  = (const float*)d_in[2];
    const float* proj_in_b  = (const float*)d_in[3];
    const float* ga         = (const float*)d_in[4];
    const float* gf         = (const float*)d_in[5];
    const float* Wq         = (const float*)d_in[6];
    const float* Wk         = (const float*)d_in[7];
    const float* Wv         = (const float*)d_in[8];
    const float* Wo         = (const float*)d_in[9];
    const float* bo         = (const float*)d_in[10];
    const float* relpos     = (const float*)d_in[11];
    const float* W1         = (const float*)d_in[12];
    const float* b1         = (const float*)d_in[13];
    const float* W2         = (const float*)d_in[14];
    const float* b2         = (const float*)d_in[15];
    const float* ln_g       = (const float*)d_in[16];
    const float* ln_b       = (const float*)d_in[17];
    const float* proj_out_w = (const float*)d_in[18];
    const float* proj_out_b = (const float*)d_in[19];
    const float* cls_w      = (const float*)d_in[20];
    const float* cls_b      = (const float*)d_in[21];
    float* outp = (float*)d_out;

    float *px, *ph, *phn, *pq, *pk, *pv, *po, *pff, *pout;
    cudaGetSymbolAddress((void**)&px,  g_x);
    cudaGetSymbolAddress((void**)&ph,  g_h);
    cudaGetSymbolAddress((void**)&phn, g_hn);
    cudaGetSymbolAddress((void**)&pq,  g_q);
    cudaGetSymbolAddress((void**)&pk,  g_k);
    cudaGetSymbolAddress((void**)&pv,  g_v);
    cudaGetSymbolAddress((void**)&po,  g_o);
    cudaGetSymbolAddress((void**)&pff, g_ff);
    cudaGetSymbolAddress((void**)&pout,g_out2);

    cudaFuncSetAttribute(tgemm_kernel<0,false>, cudaFuncAttributeMaxDynamicSharedMemorySize, GEMM_SMEM);
    cudaFuncSetAttribute(tgemm_kernel<1,false>, cudaFuncAttributeMaxDynamicSharedMemorySize, GEMM_SMEM);
    cudaFuncSetAttribute(tgemm_kernel<2,false>, cudaFuncAttributeMaxDynamicSharedMemorySize, GEMM_SMEM);
    cudaFuncSetAttribute(tgemm_kernel<3,false>, cudaFuncAttributeMaxDynamicSharedMemorySize, GEMM_SMEM);
    cudaFuncSetAttribute(tgemm_kernel<1,true>,  cudaFuncAttributeMaxDynamicSharedMemorySize, GEMM_SMEM);
    cudaFuncSetAttribute(flash_attn_kernel,     cudaFuncAttributeMaxDynamicSharedMemorySize, FLASH_SMEM);

    bias_table_kernel<<<4, 256>>>(relpos);
    embed_kernel<<<MTOT, 256>>>(saml, emb_table);

    tgemm_kernel<1,false><<<gemm_grid(DMODEL), 256, GEMM_SMEM>>>(MTOT, DMODEL, DIN,
        px, DIN, proj_in_w, DMODEL, proj_in_b, nullptr, 0, ph, DMODEL);

    for (int l = 0; l < 6; l++) {
        const float* wq = Wq + (long)l*DMODEL*DMODEL;
        const float* wk = Wk + (long)l*DMODEL*DMODEL;
        const float* wv = Wv + (long)l*DMODEL*DMODEL;
        const float* wo = Wo + (long)l*DMODEL*DMODEL;
        const float* w1 = W1 + (long)l*DMODEL*DFF;
        const float* w2 = W2 + (long)l*DFF*DMODEL;

        scalenorm_kernel<<<MTOT, 256>>>(ph, phn, ga + l);
        tgemm_kernel<0,false><<<gemm_grid(DMODEL), 256, GEMM_SMEM>>>(MTOT, DMODEL, DMODEL,
            phn, DMODEL, wq, DMODEL, nullptr, nullptr, 0, pq, DMODEL);
        tgemm_kernel<0,false><<<gemm_grid(DMODEL), 256, GEMM_SMEM>>>(MTOT, DMODEL, DMODEL,
            phn, DMODEL, wk, DMODEL, nullptr, nullptr, 0, pk, DMODEL);
        tgemm_kernel<0,false><<<gemm_grid(DMODEL), 256, GEMM_SMEM>>>(MTOT, DMODEL, DMODEL,
            phn, DMODEL, wv, DMODEL, nullptr, nullptr, 0, pv, DMODEL);
        rotary_kernel<<<(MTOT*NHEADS*16 + 255)/256, 256>>>(pq, pk);
        flash_attn_kernel<<<dim3(SEQ/64, BATCH*NHEADS), 256, FLASH_SMEM>>>(pq, pk, pv, po);
        tgemm_kernel<2,false><<<gemm_grid(DMODEL), 256, GEMM_SMEM>>>(MTOT, DMODEL, DMODEL,
            po, DMODEL, wo, DMODEL, bo + (long)l*DMODEL, ph, DMODEL, ph, DMODEL);
        scalenorm_kernel<<<MTOT, 256>>>(ph, phn, gf + l);
        tgemm_kernel<3,false><<<gemm_grid(DFF), 256, GEMM_SMEM>>>(MTOT, DFF, DMODEL,
            phn, DMODEL, w1, DFF, b1 + (long)l*DFF, nullptr, 0, pff, DFF);
        tgemm_kernel<2,false><<<gemm_grid(DMODEL), 256, GEMM_SMEM>>>(MTOT, DMODEL, DFF,
            pff, DFF, w2, DMODEL, b2 + (long)l*DMODEL, ph, DMODEL, ph, DMODEL);
    }

    layernorm_kernel<<<MTOT, 256>>>(ph, ln_g, ln_b);
    tgemm_kernel<1,false><<<gemm_grid(DIN), 256, GEMM_SMEM>>>(MTOT, DIN, DMODEL,
        ph, DMODEL, proj_out_w, DIN, proj_out_b, nullptr, 0, pout, DIN);
    tgemm_kernel<1,true><<<gemm_grid(NCLS), 256, GEMM_SMEM>>>(MTOT, NCLS, DMODEL,
        pout, DIN, cls_w, NCLS, cls_b, nullptr, 0, outp, 0);
    tail_kernel<<<(MTOT*12 + 255)/256, 256>>>(outp);
}